// round 14
// baseline (speedup 1.0000x reference)
#include <cuda_runtime.h>
#include <math.h>

// ---------------------------------------------------------------------------
// Problem constants
//   B=2, H=W=256, CD=TD=128, C=256, WS=8, SHIFT=4, NH=4, HD=32
//   M = B*H*W = 131072 pixels; window count NW=1024, N=64 per window.
// ---------------------------------------------------------------------------
#define MPIX (2 * 256 * 256)

// Scratch (device globals: allocation-free per harness rules)
__device__ float g_convx [(size_t)MPIX * 128];
__device__ float g_transx[(size_t)MPIX * 128];
__device__ float g_r     [(size_t)MPIX * 128];
__device__ float g_h     [(size_t)MPIX * 128];
__device__ float g_qkv   [(size_t)MPIX * 384];
__device__ float g_attn  [(size_t)MPIX * 128];
__device__ float g_t     [(size_t)MPIX * 128];
__device__ float g_mlp   [(size_t)MPIX * 512];

enum { M_C1 = 0, M_QKV, M_PROJ, M_GELU, M_MLP2, M_C2 };

// ---------------------------------------------------------------------------
// Generic tiled GEMM: OUT[m][n] = sum_k A[m][k] * W[k][n]  (+ mode epilogue)
// BM=BN=128, BK=16, 256 threads, 8x8 per-thread tile, double-buffered smem.
// ---------------------------------------------------------------------------
template <int K, int N, int MODE>
__global__ __launch_bounds__(256, 2)
void gemm_kernel(const float* __restrict__ A, const float* __restrict__ A2,
                 const float* __restrict__ Wm, const float* __restrict__ bias,
                 const float* __restrict__ res, float* __restrict__ out,
                 float* __restrict__ out2)
{
    constexpr int BM = 128, BN = 128, BK = 16;
    constexpr int KC = K / BK;
    __shared__ float As[2][BK][BM + 4];
    __shared__ float Bs[2][BK][BN];

    const int tid = threadIdx.x;
    const int m0 = blockIdx.y * BM;
    const int n0 = blockIdx.x * BN;
    const int tx = tid & 15;
    const int ty = tid >> 4;

    float acc[8][8];
#pragma unroll
    for (int i = 0; i < 8; ++i)
#pragma unroll
        for (int j = 0; j < 8; ++j) acc[i][j] = 0.f;

    float4 ar[2], br[2];

    auto gload = [&](int kc) {
#pragma unroll
        for (int it = 0; it < 2; ++it) {
            int idx4 = tid + it * 256;           // 512 float4 slots of A tile
            int ml = idx4 >> 2;
            int kl = (idx4 & 3) << 2;
            int m = m0 + ml;
            int k = kc * BK + kl;
            const float* src;
            if (MODE == M_C2) {                   // A = concat(convx, t) along K
                src = (k < 128) ? (A  + (size_t)m * 128 + k)
                                : (A2 + (size_t)m * 128 + (k - 128));
            } else {
                src = A + (size_t)m * K + k;
            }
            ar[it] = *(const float4*)src;
        }
#pragma unroll
        for (int it = 0; it < 2; ++it) {
            int idx4 = tid + it * 256;           // 512 float4 slots of B tile
            int kl = idx4 >> 5;
            int nl = (idx4 & 31) << 2;
            br[it] = *(const float4*)(Wm + (size_t)(kc * BK + kl) * N + n0 + nl);
        }
    };
    auto sstore = [&](int buf) {
#pragma unroll
        for (int it = 0; it < 2; ++it) {
            int idx4 = tid + it * 256;
            int ml = idx4 >> 2;
            int kl = (idx4 & 3) << 2;
            As[buf][kl + 0][ml] = ar[it].x;
            As[buf][kl + 1][ml] = ar[it].y;
            As[buf][kl + 2][ml] = ar[it].z;
            As[buf][kl + 3][ml] = ar[it].w;
        }
#pragma unroll
        for (int it = 0; it < 2; ++it) {
            int idx4 = tid + it * 256;
            int kl = idx4 >> 5;
            int nl = (idx4 & 31) << 2;
            *(float4*)&Bs[buf][kl][nl] = br[it];
        }
    };

    gload(0);
    sstore(0);
    __syncthreads();

    for (int kc = 0; kc < KC; ++kc) {
        int buf = kc & 1;
        if (kc + 1 < KC) gload(kc + 1);
#pragma unroll
        for (int kk = 0; kk < BK; ++kk) {
            float a[8], b[8];
            *(float4*)&a[0] = *(const float4*)&As[buf][kk][ty * 8];
            *(float4*)&a[4] = *(const float4*)&As[buf][kk][ty * 8 + 4];
            *(float4*)&b[0] = *(const float4*)&Bs[buf][kk][tx * 8];
            *(float4*)&b[4] = *(const float4*)&Bs[buf][kk][tx * 8 + 4];
#pragma unroll
            for (int i = 0; i < 8; ++i)
#pragma unroll
                for (int j = 0; j < 8; ++j)
                    acc[i][j] += a[i] * b[j];
        }
        if (kc + 1 < KC) sstore(buf ^ 1);
        __syncthreads();
    }

    // Epilogue
#pragma unroll
    for (int i = 0; i < 8; ++i) {
        int m = m0 + ty * 8 + i;
        size_t mout = 0;
        if (MODE == M_PROJ) {
            // window-layout m = b*65536 + w*64 + idx -> pixel index (unshift roll)
            int b   = m >> 16;
            int w   = (m >> 6) & 1023;
            int idx = m & 63;
            int sh = ((w >> 5) << 3) + (idx >> 3);
            int sw = ((w & 31) << 3) + (idx & 7);
            int oh = (sh + 4) & 255;
            int ow = (sw + 4) & 255;
            mout = (size_t)((b << 16) + (oh << 8) + ow);
        }
#pragma unroll
        for (int j = 0; j < 8; ++j) {
            int n = n0 + tx * 8 + j;
            float v = acc[i][j] + bias[n];
            if (MODE == M_C1) {
                if (n < 128) out [(size_t)m * 128 + n]        = v;
                else         out2[(size_t)m * 128 + (n - 128)] = v;
            } else if (MODE == M_QKV) {
                out[(size_t)m * N + n] = v;
            } else if (MODE == M_PROJ) {
                out[mout * 128 + n] = res[mout * 128 + n] + v;   // t = trans_x + wmsa
            } else if (MODE == M_GELU) {
                out[(size_t)m * N + n] =
                    0.5f * v * (1.0f + erff(v * 0.70710678118654752f));
            } else if (MODE == M_MLP2) {
                out[(size_t)m * 128 + n] = res[(size_t)m * 128 + n] + v;  // t += mlp
            } else { // M_C2: final residual with original input x
                out[(size_t)m * 256 + n] = res[(size_t)m * 256 + n] + v;
            }
        }
    }
}

// ---------------------------------------------------------------------------
// 3x3 SAME conv as implicit GEMM: K = 9*128 = 1152, N = 128.
// MODE 0: out = lrelu(acc + bias)          (r = lrelu(conv1(conv_x)))
// MODE 1: out = lrelu(acc + bias) + 2*out  (conv_x = r2 + 2*conv_x, in-place)
// ---------------------------------------------------------------------------
template <int MODE>
__global__ __launch_bounds__(256, 2)
void conv3x3_kernel(const float* __restrict__ src, const float* __restrict__ Wm,
                    const float* __restrict__ bias, float* __restrict__ out)
{
    constexpr int BM = 128, BN = 128, BK = 16, K = 1152;
    constexpr int KC = K / BK;
    __shared__ float As[2][BK][BM + 4];
    __shared__ float Bs[2][BK][BN];

    const int tid = threadIdx.x;
    const int m0 = blockIdx.y * BM;       // 128 consecutive pixels: same (b,h)
    const int tx = tid & 15;
    const int ty = tid >> 4;
    const int bb    = m0 >> 16;
    const int h     = (m0 >> 8) & 255;
    const int wbase = m0 & 255;           // 0 or 128

    float acc[8][8];
#pragma unroll
    for (int i = 0; i < 8; ++i)
#pragma unroll
        for (int j = 0; j < 8; ++j) acc[i][j] = 0.f;

    float4 ar[2], br[2];

    auto gload = [&](int kc) {
        int k0   = kc * BK;
        int kh   = k0 / 384;
        int kwr  = (k0 / 128) % 3;
        int cin0 = k0 & 127;
        int ih   = h + kh - 1;
        bool rowok = ((unsigned)ih < 256u);
#pragma unroll
        for (int it = 0; it < 2; ++it) {
            int idx4 = tid + it * 256;
            int ml = idx4 >> 2;
            int kl = (idx4 & 3) << 2;
            int iw = wbase + ml + kwr - 1;
            float4 v = make_float4(0.f, 0.f, 0.f, 0.f);
            if (rowok && (unsigned)iw < 256u)
                v = *(const float4*)(src +
                        (((size_t)bb * 256 + ih) * 256 + iw) * 128 + cin0 + kl);
            ar[it] = v;
        }
#pragma unroll
        for (int it = 0; it < 2; ++it) {
            int idx4 = tid + it * 256;
            int kl = idx4 >> 5;
            int nl = (idx4 & 31) << 2;
            br[it] = *(const float4*)(Wm + (size_t)(k0 + kl) * 128 + nl);
        }
    };
    auto sstore = [&](int buf) {
#pragma unroll
        for (int it = 0; it < 2; ++it) {
            int idx4 = tid + it * 256;
            int ml = idx4 >> 2;
            int kl = (idx4 & 3) << 2;
            As[buf][kl + 0][ml] = ar[it].x;
            As[buf][kl + 1][ml] = ar[it].y;
            As[buf][kl + 2][ml] = ar[it].z;
            As[buf][kl + 3][ml] = ar[it].w;
        }
#pragma unroll
        for (int it = 0; it < 2; ++it) {
            int idx4 = tid + it * 256;
            int kl = idx4 >> 5;
            int nl = (idx4 & 31) << 2;
            *(float4*)&Bs[buf][kl][nl] = br[it];
        }
    };

    gload(0);
    sstore(0);
    __syncthreads();

    for (int kc = 0; kc < KC; ++kc) {
        int buf = kc & 1;
        if (kc + 1 < KC) gload(kc + 1);
#pragma unroll
        for (int kk = 0; kk < BK; ++kk) {
            float a[8], b[8];
            *(float4*)&a[0] = *(const float4*)&As[buf][kk][ty * 8];
            *(float4*)&a[4] = *(const float4*)&As[buf][kk][ty * 8 + 4];
            *(float4*)&b[0] = *(const float4*)&Bs[buf][kk][tx * 8];
            *(float4*)&b[4] = *(const float4*)&Bs[buf][kk][tx * 8 + 4];
#pragma unroll
            for (int i = 0; i < 8; ++i)
#pragma unroll
                for (int j = 0; j < 8; ++j)
                    acc[i][j] += a[i] * b[j];
        }
        if (kc + 1 < KC) sstore(buf ^ 1);
        __syncthreads();
    }

#pragma unroll
    for (int i = 0; i < 8; ++i) {
        int m = m0 + ty * 8 + i;
#pragma unroll
        for (int j = 0; j < 8; ++j) {
            int n = tx * 8 + j;
            float v = acc[i][j] + bias[n];
            v = (v >= 0.f) ? v : 0.01f * v;           // leaky relu
            if (MODE == 0) out[(size_t)m * 128 + n] = v;
            else           out[(size_t)m * 128 + n] = v + 2.f * out[(size_t)m * 128 + n];
        }
    }
}

// ---------------------------------------------------------------------------
// LayerNorm over last dim (128). One warp per pixel, float4 per lane.
// ---------------------------------------------------------------------------
__global__ void ln_kernel(const float* __restrict__ src, const float* __restrict__ g,
                          const float* __restrict__ beta, float* __restrict__ dst)
{
    int gid = blockIdx.x * blockDim.x + threadIdx.x;
    int pix = gid >> 5;
    int lane = gid & 31;
    if (pix >= MPIX) return;

    float4 v = ((const float4*)(src + (size_t)pix * 128))[lane];
    float s  = v.x + v.y + v.z + v.w;
    float sq = v.x * v.x + v.y * v.y + v.z * v.z + v.w * v.w;
#pragma unroll
    for (int o = 16; o > 0; o >>= 1) {
        s  += __shfl_xor_sync(0xffffffffu, s,  o);
        sq += __shfl_xor_sync(0xffffffffu, sq, o);
    }
    float mu  = s * (1.f / 128.f);
    float var = sq * (1.f / 128.f) - mu * mu;
    float inv = rsqrtf(var + 1e-5f);

    float4 gg = ((const float4*)g)[lane];
    float4 bb = ((const float4*)beta)[lane];
    float4 o4;
    o4.x = (v.x - mu) * inv * gg.x + bb.x;
    o4.y = (v.y - mu) * inv * gg.y + bb.y;
    o4.z = (v.z - mu) * inv * gg.z + bb.z;
    o4.w = (v.w - mu) * inv * gg.w + bb.w;
    ((float4*)(dst + (size_t)pix * 128))[lane] = o4;
}

// ---------------------------------------------------------------------------
// Shifted-window attention. One block per (batch, window). 256 threads:
// thread = (head 0..3) x (row i 0..63). Shift mask + rel-pos bias computed
// analytically. Q gathered from gmem, K/V staged (sequentially) in smem.
// ---------------------------------------------------------------------------
__global__ __launch_bounds__(256)
void attn_kernel(const float* __restrict__ qkv, const float* __restrict__ rpb,
                 float* __restrict__ out)
{
    __shared__ float kv[64][128];      // holds K, then reused for V
    __shared__ float rpbs[900];        // 225 x 4
    __shared__ int   msrc[64];
    __shared__ int   regid[64];

    const int bw = blockIdx.x;         // 0..2047
    const int b  = bw >> 10;
    const int w  = bw & 1023;
    const int wh = w >> 5, ww = w & 31;
    const int tid = threadIdx.x;

    if (tid < 64) {
        int ih = tid >> 3, iw = tid & 7;
        int sh = wh * 8 + ih, sw = ww * 8 + iw;
        int oh = (sh + 4) & 255, ow = (sw + 4) & 255;   // roll(-4) gather
        msrc[tid] = (b * 256 + oh) * 256 + ow;
        int rr = (sh < 248) ? 0 : (sh < 252 ? 1 : 2);
        int cr = (sw < 248) ? 0 : (sw < 252 ? 1 : 2);
        regid[tid] = rr * 3 + cr;
    }
    for (int i = tid; i < 900; i += 256) rpbs[i] = rpb[i];
    __syncthreads();

    // ---- load K ----
#pragma unroll
    for (int it = 0; it < 8; ++it) {
        int slot = tid + it * 256;     // 2048 float4 slots
        int r = slot >> 5, c4 = slot & 31;
        size_t base = (size_t)msrc[r] * 384;
        *(float4*)&kv[r][c4 * 4] = *(const float4*)(qkv + base + 128 + c4 * 4);
    }
    __syncthreads();

    const int hd = tid >> 6;           // head
    const int i  = tid & 63;           // query row in window
    const float SCALE = 0.17677669529663687f;  // 32^-0.5

    float q[32];
    {
        size_t qb = (size_t)msrc[i] * 384 + hd * 32;
#pragma unroll
        for (int d4 = 0; d4 < 8; ++d4) {
            float4 t = *(const float4*)(qkv + qb + d4 * 4);
            q[d4 * 4 + 0] = t.x; q[d4 * 4 + 1] = t.y;
            q[d4 * 4 + 2] = t.z; q[d4 * 4 + 3] = t.w;
        }
    }

    float sc[64];
    const int idi = regid[i];
    const int ihh = i >> 3, iww = i & 7;
    float mx = -1e30f;
#pragma unroll
    for (int j = 0; j < 64; ++j) {
        float s = 0.f;
        const float* kr = &kv[j][hd * 32];
#pragma unroll
        for (int d = 0; d < 32; d += 4) {
            float4 kk = *(const float4*)(kr + d);
            s += q[d] * kk.x + q[d + 1] * kk.y + q[d + 2] * kk.z + q[d + 3] * kk.w;
        }
        s *= SCALE;
        int jh = j >> 3, jw = j & 7;
        int rel = (ihh - jh + 7) * 15 + (iww - jw + 7);
        s += rpbs[rel * 4 + hd];
        if (regid[j] != idi) s -= 1e9f;
        sc[j] = s;
        mx = fmaxf(mx, s);
    }
    float sum = 0.f;
#pragma unroll
    for (int j = 0; j < 64; ++j) {
        float e = expf(sc[j] - mx);
        sc[j] = e;
        sum += e;
    }
    float rinv = 1.f / sum;
    __syncthreads();                   // everyone done with K

    // ---- load V into same smem ----
#pragma unroll
    for (int it = 0; it < 8; ++it) {
        int slot = tid + it * 256;
        int r = slot >> 5, c4 = slot & 31;
        size_t base = (size_t)msrc[r] * 384;
        *(float4*)&kv[r][c4 * 4] = *(const float4*)(qkv + base + 256 + c4 * 4);
    }
    __syncthreads();

    float o[32];
#pragma unroll
    for (int d = 0; d < 32; ++d) o[d] = 0.f;
#pragma unroll
    for (int j = 0; j < 64; ++j) {
        float p = sc[j] * rinv;
        const float* vr = &kv[j][hd * 32];
#pragma unroll
        for (int d = 0; d < 32; d += 4) {
            float4 vv = *(const float4*)(vr + d);
            o[d]     += p * vv.x;
            o[d + 1] += p * vv.y;
            o[d + 2] += p * vv.z;
            o[d + 3] += p * vv.w;
        }
    }
    float* op = out + ((size_t)bw * 64 + i) * 128 + hd * 32;
#pragma unroll
    for (int d4 = 0; d4 < 8; ++d4)
        *(float4*)(op + d4 * 4) = make_float4(o[d4 * 4], o[d4 * 4 + 1],
                                              o[d4 * 4 + 2], o[d4 * 4 + 3]);
}

// ---------------------------------------------------------------------------
// Launcher: 11 launches, all default stream, graph-capturable, alloc-free.
// ---------------------------------------------------------------------------
extern "C" void kernel_launch(void* const* d_in, const int* in_sizes, int n_in,
                              void* d_out, int out_size)
{
    const float* x    = (const float*)d_in[0];
    const float* c1w  = (const float*)d_in[1];
    const float* c1b  = (const float*)d_in[2];
    const float* rw1  = (const float*)d_in[3];
    const float* rb1  = (const float*)d_in[4];
    const float* rw2  = (const float*)d_in[5];
    const float* rb2  = (const float*)d_in[6];
    const float* ln1g = (const float*)d_in[7];
    const float* ln1b = (const float*)d_in[8];
    const float* qkvw = (const float*)d_in[9];
    const float* qkvb = (const float*)d_in[10];
    const float* rpb  = (const float*)d_in[11];
    const float* pw   = (const float*)d_in[12];
    const float* pb   = (const float*)d_in[13];
    const float* ln2g = (const float*)d_in[14];
    const float* ln2b = (const float*)d_in[15];
    const float* mw1  = (const float*)d_in[16];
    const float* mb1  = (const float*)d_in[17];
    const float* mw2  = (const float*)d_in[18];
    const float* mb2  = (const float*)d_in[19];
    const float* c2w  = (const float*)d_in[20];
    const float* c2b  = (const float*)d_in[21];
    float* out = (float*)d_out;

    float *convx, *transx, *r, *h, *qkv, *attn, *t, *mlp;
    cudaGetSymbolAddress((void**)&convx,  g_convx);
    cudaGetSymbolAddress((void**)&transx, g_transx);
    cudaGetSymbolAddress((void**)&r,      g_r);
    cudaGetSymbolAddress((void**)&h,      g_h);
    cudaGetSymbolAddress((void**)&qkv,    g_qkv);
    cudaGetSymbolAddress((void**)&attn,   g_attn);
    cudaGetSymbolAddress((void**)&t,      g_t);
    cudaGetSymbolAddress((void**)&mlp,    g_mlp);

    dim3 blk(256);
    const int MB = MPIX / 128;   // 1024 M-tiles

    // 1. c1 (1x1 conv) -> split conv_x / trans_x
    gemm_kernel<256, 256, M_C1><<<dim3(2, MB), blk>>>(x, nullptr, c1w, c1b,
                                                      nullptr, convx, transx);
    // 2-3. conv branch: two 3x3 convs + lrelu, residual 2*conv_x
    conv3x3_kernel<0><<<dim3(1, MB), blk>>>(convx, rw1, rb1, r);
    conv3x3_kernel<1><<<dim3(1, MB), blk>>>(r, rw2, rb2, convx);

    // 4. LN1(trans_x) -> h
    ln_kernel<<<MPIX / 8, 256>>>(transx, ln1g, ln1b, h);
    // 5. qkv projection
    gemm_kernel<128, 384, M_QKV><<<dim3(3, MB), blk>>>(h, nullptr, qkvw, qkvb,
                                                       nullptr, qkv, nullptr);
    // 6. shifted-window attention (window layout out)
    attn_kernel<<<2048, 256>>>(qkv, rpb, attn);
    // 7. proj + unshift scatter + trans_x residual -> t
    gemm_kernel<128, 128, M_PROJ><<<dim3(1, MB), blk>>>(attn, nullptr, pw, pb,
                                                        transx, t, nullptr);
    // 8. LN2(t) -> h
    ln_kernel<<<MPIX / 8, 256>>>(t, ln2g, ln2b, h);
    // 9. MLP up + exact GELU
    gemm_kernel<128, 512, M_GELU><<<dim3(4, MB), blk>>>(h, nullptr, mw1, mb1,
                                                        nullptr, mlp, nullptr);
    // 10. MLP down + t residual (in-place)
    gemm_kernel<512, 128, M_MLP2><<<dim3(1, MB), blk>>>(mlp, nullptr, mw2, mb2,
                                                        t, t, nullptr);
    // 11. c2 on concat(conv_x, t) + x residual -> out
    gemm_kernel<256, 256, M_C2><<<dim3(2, MB), blk>>>(convx, t, c2w, c2b,
                                                      x, out, nullptr);
}

// round 15
// speedup vs baseline: 2.4451x; 2.4451x over previous
#include <cuda_runtime.h>
#include <math.h>

// ---------------------------------------------------------------------------
// Problem constants
//   B=2, H=W=256, CD=TD=128, C=256, WS=8, SHIFT=4, NH=4, HD=32
//   M = B*H*W = 131072 pixels; window count NW=1024, N=64 per window.
// ---------------------------------------------------------------------------
#define MPIX (2 * 256 * 256)

// Scratch (device globals: allocation-free per harness rules)
__device__ float g_convx [(size_t)MPIX * 128];
__device__ float g_transx[(size_t)MPIX * 128];
__device__ float g_r     [(size_t)MPIX * 128];
__device__ float g_h     [(size_t)MPIX * 128];
__device__ float g_qkv   [(size_t)MPIX * 384];
__device__ float g_attn  [(size_t)MPIX * 128];
__device__ float g_t     [(size_t)MPIX * 128];
__device__ float g_mlp   [(size_t)MPIX * 512];

enum { M_C1 = 0, M_QKV, M_PROJ, M_GELU, M_MLP2, M_C2 };

// ---------------------------------------------------------------------------
// tf32 helpers
// ---------------------------------------------------------------------------
__device__ __forceinline__ float to_tf32(float x) {
    float r;
    asm("cvt.rna.tf32.f32 %0, %1;" : "=f"(r) : "f"(x));
    return r;
}

__device__ __forceinline__ void mma_tf32(float d[4], const unsigned a[4],
                                         const unsigned b[2]) {
    asm volatile(
        "mma.sync.aligned.m16n8k8.row.col.f32.tf32.tf32.f32 "
        "{%0,%1,%2,%3}, {%4,%5,%6,%7}, {%8,%9}, {%0,%1,%2,%3};"
        : "+f"(d[0]), "+f"(d[1]), "+f"(d[2]), "+f"(d[3])
        : "r"(a[0]), "r"(a[1]), "r"(a[2]), "r"(a[3]), "r"(b[0]), "r"(b[1]));
}

// One BK=16 chunk of MMAs for one warp (2 k8 steps, 4x4 fragment grid).
// As/Bs: [16][136] tf32-valued smem tiles ([k][m] / [k][n]).
__device__ __forceinline__ void mma_chunk(const float (*As)[136],
                                          const float (*Bs)[136],
                                          int wm, int wn, int g, int tg,
                                          float (*dacc)[4][4]) {
#pragma unroll
    for (int ks = 0; ks < 2; ++ks) {
        const int k0 = ks * 8;
        unsigned afr[4][4], bfr[4][2];
#pragma unroll
        for (int i = 0; i < 4; ++i) {
            int mb = wm * 64 + i * 16;
            afr[i][0] = __float_as_uint(As[k0 + tg    ][mb + g]);
            afr[i][1] = __float_as_uint(As[k0 + tg    ][mb + g + 8]);
            afr[i][2] = __float_as_uint(As[k0 + tg + 4][mb + g]);
            afr[i][3] = __float_as_uint(As[k0 + tg + 4][mb + g + 8]);
        }
#pragma unroll
        for (int j = 0; j < 4; ++j) {
            int nb = wn * 32 + j * 8;
            bfr[j][0] = __float_as_uint(Bs[k0 + tg    ][nb + g]);
            bfr[j][1] = __float_as_uint(Bs[k0 + tg + 4][nb + g]);
        }
#pragma unroll
        for (int i = 0; i < 4; ++i)
#pragma unroll
            for (int j = 0; j < 4; ++j)
                mma_tf32(dacc[i][j], afr[i], bfr[j]);
    }
}

// ---------------------------------------------------------------------------
// Generic tiled GEMM (tf32 tensor cores): OUT = A @ W + epilogue
// BM=BN=128, BK=16, 256 threads (8 warps 2x4), warp tile 64x32, m16n8k8 mma.
// ---------------------------------------------------------------------------
template <int K, int N, int MODE>
__global__ __launch_bounds__(256, 2)
void gemm_kernel(const float* __restrict__ A, const float* __restrict__ A2,
                 const float* __restrict__ Wm, const float* __restrict__ bias,
                 const float* __restrict__ res, float* __restrict__ out,
                 float* __restrict__ out2)
{
    constexpr int BM = 128, BK = 16;
    constexpr int KC = K / BK;
    __shared__ float As[2][BK][136];
    __shared__ float Bs[2][BK][136];

    const int tid = threadIdx.x;
    const int m0 = blockIdx.y * BM;
    const int n0 = blockIdx.x * 128;
    const int lane = tid & 31, wid = tid >> 5;
    const int wm = wid >> 2, wn = wid & 3;      // 2 x 4 warp grid
    const int g = lane >> 2, tg = lane & 3;

    float dacc[4][4][4];
#pragma unroll
    for (int i = 0; i < 4; ++i)
#pragma unroll
        for (int j = 0; j < 4; ++j)
#pragma unroll
            for (int r = 0; r < 4; ++r) dacc[i][j][r] = 0.f;

    float4 ar[2], br[2];

    auto gload = [&](int kc) {
#pragma unroll
        for (int it = 0; it < 2; ++it) {
            int idx4 = tid + it * 256;           // 512 float4 slots of A tile
            int ml = idx4 >> 2;
            int kl = (idx4 & 3) << 2;
            int m = m0 + ml;
            int k = kc * BK + kl;
            const float* src;
            if (MODE == M_C2) {                   // A = concat(convx, t) along K
                src = (k < 128) ? (A  + (size_t)m * 128 + k)
                                : (A2 + (size_t)m * 128 + (k - 128));
            } else {
                src = A + (size_t)m * K + k;
            }
            ar[it] = *(const float4*)src;
        }
#pragma unroll
        for (int it = 0; it < 2; ++it) {
            int idx4 = tid + it * 256;           // 512 float4 slots of B tile
            int kl = idx4 >> 5;
            int nl = (idx4 & 31) << 2;
            br[it] = *(const float4*)(Wm + (size_t)(kc * BK + kl) * N + n0 + nl);
        }
    };
    auto sstore = [&](int buf) {
#pragma unroll
        for (int it = 0; it < 2; ++it) {
            int idx4 = tid + it * 256;
            int ml = idx4 >> 2;
            int kl = (idx4 & 3) << 2;
            As[buf][kl + 0][ml] = to_tf32(ar[it].x);
            As[buf][kl + 1][ml] = to_tf32(ar[it].y);
            As[buf][kl + 2][ml] = to_tf32(ar[it].z);
            As[buf][kl + 3][ml] = to_tf32(ar[it].w);
        }
#pragma unroll
        for (int it = 0; it < 2; ++it) {
            int idx4 = tid + it * 256;
            int kl = idx4 >> 5;
            int nl = (idx4 & 31) << 2;
            float4 v;
            v.x = to_tf32(br[it].x); v.y = to_tf32(br[it].y);
            v.z = to_tf32(br[it].z); v.w = to_tf32(br[it].w);
            *(float4*)&Bs[buf][kl][nl] = v;
        }
    };

    gload(0);
    sstore(0);
    __syncthreads();

    for (int kc = 0; kc < KC; ++kc) {
        int buf = kc & 1;
        if (kc + 1 < KC) gload(kc + 1);
        mma_chunk(As[buf], Bs[buf], wm, wn, g, tg, dacc);
        if (kc + 1 < KC) sstore(buf ^ 1);
        __syncthreads();
    }

    // Epilogue: d0/d1 are adjacent columns -> float2 stores.
#pragma unroll
    for (int i = 0; i < 4; ++i) {
#pragma unroll
        for (int r2 = 0; r2 < 2; ++r2) {
            int m = m0 + wm * 64 + i * 16 + g + r2 * 8;
            size_t mout = 0;
            if (MODE == M_PROJ) {
                // window-layout m = b*65536 + w*64 + idx -> pixel (unshift roll)
                int b   = m >> 16;
                int w   = (m >> 6) & 1023;
                int idx = m & 63;
                int sh = ((w >> 5) << 3) + (idx >> 3);
                int sw = ((w & 31) << 3) + (idx & 7);
                int oh = (sh + 4) & 255;
                int ow = (sw + 4) & 255;
                mout = (size_t)((b << 16) + (oh << 8) + ow);
            }
#pragma unroll
            for (int j = 0; j < 4; ++j) {
                int n = n0 + wn * 32 + j * 8 + tg * 2;
                float v0 = dacc[i][j][r2 * 2 + 0] + bias[n];
                float v1 = dacc[i][j][r2 * 2 + 1] + bias[n + 1];
                if (MODE == M_C1) {
                    if (n < 128)
                        *(float2*)(out  + (size_t)m * 128 + n)       = make_float2(v0, v1);
                    else
                        *(float2*)(out2 + (size_t)m * 128 + n - 128) = make_float2(v0, v1);
                } else if (MODE == M_QKV) {
                    *(float2*)(out + (size_t)m * N + n) = make_float2(v0, v1);
                } else if (MODE == M_PROJ) {
                    float2 rr = *(const float2*)(res + mout * 128 + n);
                    *(float2*)(out + mout * 128 + n) =
                        make_float2(rr.x + v0, rr.y + v1);
                } else if (MODE == M_GELU) {
                    v0 = 0.5f * v0 * (1.0f + erff(v0 * 0.70710678118654752f));
                    v1 = 0.5f * v1 * (1.0f + erff(v1 * 0.70710678118654752f));
                    *(float2*)(out + (size_t)m * N + n) = make_float2(v0, v1);
                } else if (MODE == M_MLP2) {
                    float2 rr = *(const float2*)(res + (size_t)m * 128 + n);
                    *(float2*)(out + (size_t)m * 128 + n) =
                        make_float2(rr.x + v0, rr.y + v1);
                } else { // M_C2
                    float2 rr = *(const float2*)(res + (size_t)m * 256 + n);
                    *(float2*)(out + (size_t)m * 256 + n) =
                        make_float2(rr.x + v0, rr.y + v1);
                }
            }
        }
    }
}

// ---------------------------------------------------------------------------
// 3x3 SAME conv as implicit GEMM (tf32 tensor cores): K=1152, N=128.
// MODE 0: out = lrelu(acc+bias)      MODE 1: out = lrelu(acc+bias) + 2*out
// ---------------------------------------------------------------------------
template <int MODE>
__global__ __launch_bounds__(256, 2)
void conv3x3_kernel(const float* __restrict__ src, const float* __restrict__ Wm,
                    const float* __restrict__ bias, float* __restrict__ out)
{
    constexpr int BK = 16, K = 1152;
    constexpr int KC = K / BK;
    __shared__ float As[2][BK][136];
    __shared__ float Bs[2][BK][136];

    const int tid = threadIdx.x;
    const int m0 = blockIdx.y * 128;      // 128 consecutive pixels: same (b,h)
    const int lane = tid & 31, wid = tid >> 5;
    const int wm = wid >> 2, wn = wid & 3;
    const int g = lane >> 2, tg = lane & 3;
    const int bb    = m0 >> 16;
    const int h     = (m0 >> 8) & 255;
    const int wbase = m0 & 255;           // 0 or 128

    float dacc[4][4][4];
#pragma unroll
    for (int i = 0; i < 4; ++i)
#pragma unroll
        for (int j = 0; j < 4; ++j)
#pragma unroll
            for (int r = 0; r < 4; ++r) dacc[i][j][r] = 0.f;

    float4 ar[2], br[2];

    auto gload = [&](int kc) {
        int k0   = kc * BK;
        int kh   = k0 / 384;
        int kwr  = (k0 / 128) % 3;
        int cin0 = k0 & 127;
        int ih   = h + kh - 1;
        bool rowok = ((unsigned)ih < 256u);
#pragma unroll
        for (int it = 0; it < 2; ++it) {
            int idx4 = tid + it * 256;
            int ml = idx4 >> 2;
            int kl = (idx4 & 3) << 2;
            int iw = wbase + ml + kwr - 1;
            float4 v = make_float4(0.f, 0.f, 0.f, 0.f);
            if (rowok && (unsigned)iw < 256u)
                v = *(const float4*)(src +
                        (((size_t)bb * 256 + ih) * 256 + iw) * 128 + cin0 + kl);
            ar[it] = v;
        }
#pragma unroll
        for (int it = 0; it < 2; ++it) {
            int idx4 = tid + it * 256;
            int kl = idx4 >> 5;
            int nl = (idx4 & 31) << 2;
            br[it] = *(const float4*)(Wm + (size_t)(k0 + kl) * 128 + nl);
        }
    };
    auto sstore = [&](int buf) {
#pragma unroll
        for (int it = 0; it < 2; ++it) {
            int idx4 = tid + it * 256;
            int ml = idx4 >> 2;
            int kl = (idx4 & 3) << 2;
            As[buf][kl + 0][ml] = to_tf32(ar[it].x);
            As[buf][kl + 1][ml] = to_tf32(ar[it].y);
            As[buf][kl + 2][ml] = to_tf32(ar[it].z);
            As[buf][kl + 3][ml] = to_tf32(ar[it].w);
        }
#pragma unroll
        for (int it = 0; it < 2; ++it) {
            int idx4 = tid + it * 256;
            int kl = idx4 >> 5;
            int nl = (idx4 & 31) << 2;
            float4 v;
            v.x = to_tf32(br[it].x); v.y = to_tf32(br[it].y);
            v.z = to_tf32(br[it].z); v.w = to_tf32(br[it].w);
            *(float4*)&Bs[buf][kl][nl] = v;
        }
    };

    gload(0);
    sstore(0);
    __syncthreads();

    for (int kc = 0; kc < KC; ++kc) {
        int buf = kc & 1;
        if (kc + 1 < KC) gload(kc + 1);
        mma_chunk(As[buf], Bs[buf], wm, wn, g, tg, dacc);
        if (kc + 1 < KC) sstore(buf ^ 1);
        __syncthreads();
    }

#pragma unroll
    for (int i = 0; i < 4; ++i) {
#pragma unroll
        for (int r2 = 0; r2 < 2; ++r2) {
            int m = m0 + wm * 64 + i * 16 + g + r2 * 8;
#pragma unroll
            for (int j = 0; j < 4; ++j) {
                int n = wn * 32 + j * 8 + tg * 2;
                float v0 = dacc[i][j][r2 * 2 + 0] + bias[n];
                float v1 = dacc[i][j][r2 * 2 + 1] + bias[n + 1];
                v0 = (v0 >= 0.f) ? v0 : 0.01f * v0;
                v1 = (v1 >= 0.f) ? v1 : 0.01f * v1;
                if (MODE == 0) {
                    *(float2*)(out + (size_t)m * 128 + n) = make_float2(v0, v1);
                } else {
                    float2 pr = *(const float2*)(out + (size_t)m * 128 + n);
                    *(float2*)(out + (size_t)m * 128 + n) =
                        make_float2(v0 + 2.f * pr.x, v1 + 2.f * pr.y);
                }
            }
        }
    }
}

// ---------------------------------------------------------------------------
// LayerNorm over last dim (128). One warp per pixel, float4 per lane.
// ---------------------------------------------------------------------------
__global__ void ln_kernel(const float* __restrict__ src, const float* __restrict__ g,
                          const float* __restrict__ beta, float* __restrict__ dst)
{
    int gid = blockIdx.x * blockDim.x + threadIdx.x;
    int pix = gid >> 5;
    int lane = gid & 31;
    if (pix >= MPIX) return;

    float4 v = ((const float4*)(src + (size_t)pix * 128))[lane];
    float s  = v.x + v.y + v.z + v.w;
    float sq = v.x * v.x + v.y * v.y + v.z * v.z + v.w * v.w;
#pragma unroll
    for (int o = 16; o > 0; o >>= 1) {
        s  += __shfl_xor_sync(0xffffffffu, s,  o);
        sq += __shfl_xor_sync(0xffffffffu, sq, o);
    }
    float mu  = s * (1.f / 128.f);
    float var = sq * (1.f / 128.f) - mu * mu;
    float inv = rsqrtf(var + 1e-5f);

    float4 gg = ((const float4*)g)[lane];
    float4 bb = ((const float4*)beta)[lane];
    float4 o4;
    o4.x = (v.x - mu) * inv * gg.x + bb.x;
    o4.y = (v.y - mu) * inv * gg.y + bb.y;
    o4.z = (v.z - mu) * inv * gg.z + bb.z;
    o4.w = (v.w - mu) * inv * gg.w + bb.w;
    ((float4*)(dst + (size_t)pix * 128))[lane] = o4;
}

// ---------------------------------------------------------------------------
// Shifted-window attention (fp32). One block per (batch, window).
// ---------------------------------------------------------------------------
__global__ __launch_bounds__(256)
void attn_kernel(const float* __restrict__ qkv, const float* __restrict__ rpb,
                 float* __restrict__ out)
{
    __shared__ float kv[64][128];      // holds K, then reused for V
    __shared__ float rpbs[900];        // 225 x 4
    __shared__ int   msrc[64];
    __shared__ int   regid[64];

    const int bw = blockIdx.x;         // 0..2047
    const int b  = bw >> 10;
    const int w  = bw & 1023;
    const int wh = w >> 5, ww = w & 31;
    const int tid = threadIdx.x;

    if (tid < 64) {
        int ih = tid >> 3, iw = tid & 7;
        int sh = wh * 8 + ih, sw = ww * 8 + iw;
        int oh = (sh + 4) & 255, ow = (sw + 4) & 255;   // roll(-4) gather
        msrc[tid] = (b * 256 + oh) * 256 + ow;
        int rr = (sh < 248) ? 0 : (sh < 252 ? 1 : 2);
        int cr = (sw < 248) ? 0 : (sw < 252 ? 1 : 2);
        regid[tid] = rr * 3 + cr;
    }
    for (int i = tid; i < 900; i += 256) rpbs[i] = rpb[i];
    __syncthreads();

    // ---- load K ----
#pragma unroll
    for (int it = 0; it < 8; ++it) {
        int slot = tid + it * 256;     // 2048 float4 slots
        int r = slot >> 5, c4 = slot & 31;
        size_t base = (size_t)msrc[r] * 384;
        *(float4*)&kv[r][c4 * 4] = *(const float4*)(qkv + base + 128 + c4 * 4);
    }
    __syncthreads();

    const int hd = tid >> 6;           // head
    const int i  = tid & 63;           // query row in window
    const float SCALE = 0.17677669529663687f;  // 32^-0.5

    float q[32];
    {
        size_t qb = (size_t)msrc[i] * 384 + hd * 32;
#pragma unroll
        for (int d4 = 0; d4 < 8; ++d4) {
            float4 t = *(const float4*)(qkv + qb + d4 * 4);
            q[d4 * 4 + 0] = t.x; q[d4 * 4 + 1] = t.y;
            q[d4 * 4 + 2] = t.z; q[d4 * 4 + 3] = t.w;
        }
    }

    float sc[64];
    const int idi = regid[i];
    const int ihh = i >> 3, iww = i & 7;
    float mx = -1e30f;
#pragma unroll
    for (int j = 0; j < 64; ++j) {
        float s = 0.f;
        const float* kr = &kv[j][hd * 32];
#pragma unroll
        for (int d = 0; d < 32; d += 4) {
            float4 kk = *(const float4*)(kr + d);
            s += q[d] * kk.x + q[d + 1] * kk.y + q[d + 2] * kk.z + q[d + 3] * kk.w;
        }
        s *= SCALE;
        int jh = j >> 3, jw = j & 7;
        int rel = (ihh - jh + 7) * 15 + (iww - jw + 7);
        s += rpbs[rel * 4 + hd];
        if (regid[j] != idi) s -= 1e9f;
        sc[j] = s;
        mx = fmaxf(mx, s);
    }
    float sum = 0.f;
#pragma unroll
    for (int j = 0; j < 64; ++j) {
        float e = expf(sc[j] - mx);
        sc[j] = e;
        sum += e;
    }
    float rinv = 1.f / sum;
    __syncthreads();                   // everyone done with K

    // ---- load V into same smem ----
#pragma unroll
    for (int it = 0; it < 8; ++it) {
        int slot = tid + it * 256;
        int r = slot >> 5, c4 = slot & 31;
        size_t base = (size_t)msrc[r] * 384;
        *(float4*)&kv[r][c4 * 4] = *(const float4*)(qkv + base + 256 + c4 * 4);
    }
    __syncthreads();

    float o[32];
#pragma unroll
    for (int d = 0; d < 32; ++d) o[d] = 0.f;
#pragma unroll
    for (int j = 0; j < 64; ++j) {
        float p = sc[j] * rinv;
        const float* vr = &kv[j][hd * 32];
#pragma unroll
        for (int d = 0; d < 32; d += 4) {
            float4 vv = *(const float4*)(vr + d);
            o[d]     += p * vv.x;
            o[d + 1] += p * vv.y;
            o[d + 2] += p * vv.z;
            o[d + 3] += p * vv.w;
        }
    }
    float* op = out + ((size_t)bw * 64 + i) * 128 + hd * 32;
#pragma unroll
    for (int d4 = 0; d4 < 8; ++d4)
        *(float4*)(op + d4 * 4) = make_float4(o[d4 * 4], o[d4 * 4 + 1],
                                              o[d4 * 4 + 2], o[d4 * 4 + 3]);
}

// ---------------------------------------------------------------------------
// Launcher: 11 launches, all default stream, graph-capturable, alloc-free.
// ---------------------------------------------------------------------------
extern "C" void kernel_launch(void* const* d_in, const int* in_sizes, int n_in,
                              void* d_out, int out_size)
{
    const float* x    = (const float*)d_in[0];
    const float* c1w  = (const float*)d_in[1];
    const float* c1b  = (const float*)d_in[2];
    const float* rw1  = (const float*)d_in[3];
    const float* rb1  = (const float*)d_in[4];
    const float* rw2  = (const float*)d_in[5];
    const float* rb2  = (const float*)d_in[6];
    const float* ln1g = (const float*)d_in[7];
    const float* ln1b = (const float*)d_in[8];
    const float* qkvw = (const float*)d_in[9];
    const float* qkvb = (const float*)d_in[10];
    const float* rpb  = (const float*)d_in[11];
    const float* pw   = (const float*)d_in[12];
    const float* pb   = (const float*)d_in[13];
    const float* ln2g = (const float*)d_in[14];
    const float* ln2b = (const float*)d_in[15];
    const float* mw1  = (const float*)d_in[16];
    const float* mb1  = (const float*)d_in[17];
    const float* mw2  = (const float*)d_in[18];
    const float* mb2  = (const float*)d_in[19];
    const float* c2w  = (const float*)d_in[20];
    const float* c2b  = (const float*)d_in[21];
    float* out = (float*)d_out;

    float *convx, *transx, *r, *h, *qkv, *attn, *t, *mlp;
    cudaGetSymbolAddress((void**)&convx,  g_convx);
    cudaGetSymbolAddress((void**)&transx, g_transx);
    cudaGetSymbolAddress((void**)&r,      g_r);
    cudaGetSymbolAddress((void**)&h,      g_h);
    cudaGetSymbolAddress((void**)&qkv,    g_qkv);
    cudaGetSymbolAddress((void**)&attn,   g_attn);
    cudaGetSymbolAddress((void**)&t,      g_t);
    cudaGetSymbolAddress((void**)&mlp,    g_mlp);

    dim3 blk(256);
    const int MB = MPIX / 128;   // 1024 M-tiles

    // 1. c1 (1x1 conv) -> split conv_x / trans_x
    gemm_kernel<256, 256, M_C1><<<dim3(2, MB), blk>>>(x, nullptr, c1w, c1b,
                                                      nullptr, convx, transx);
    // 2-3. conv branch: two 3x3 convs + lrelu, residual 2*conv_x
    conv3x3_kernel<0><<<dim3(1, MB), blk>>>(convx, rw1, rb1, r);
    conv3x3_kernel<1><<<dim3(1, MB), blk>>>(r, rw2, rb2, convx);

    // 4. LN1(trans_x) -> h
    ln_kernel<<<MPIX / 8, 256>>>(transx, ln1g, ln1b, h);
    // 5. qkv projection
    gemm_kernel<128, 384, M_QKV><<<dim3(3, MB), blk>>>(h, nullptr, qkvw, qkvb,
                                                       nullptr, qkv, nullptr);
    // 6. shifted-window attention (window layout out)
    attn_kernel<<<2048, 256>>>(qkv, rpb, attn);
    // 7. proj + unshift scatter + trans_x residual -> t
    gemm_kernel<128, 128, M_PROJ><<<dim3(1, MB), blk>>>(attn, nullptr, pw, pb,
                                                        transx, t, nullptr);
    // 8. LN2(t) -> h
    ln_kernel<<<MPIX / 8, 256>>>(t, ln2g, ln2b, h);
    // 9. MLP up + exact GELU
    gemm_kernel<128, 512, M_GELU><<<dim3(4, MB), blk>>>(h, nullptr, mw1, mb1,
                                                        nullptr, mlp, nullptr);
    // 10. MLP down + t residual (in-place)
    gemm_kernel<512, 128, M_MLP2><<<dim3(1, MB), blk>>>(mlp, nullptr, mw2, mb2,
                                                        t, t, nullptr);
    // 11. c2 on concat(conv_x, t) + x residual -> out
    gemm_kernel<256, 256, M_C2><<<dim3(2, MB), blk>>>(convx, t, c2w, c2b,
                                                      x, out, nullptr);
}

// round 16
// speedup vs baseline: 2.4494x; 1.0018x over previous
#include <cuda_runtime.h>
#include <math.h>

// ---------------------------------------------------------------------------
// Problem constants
//   B=2, H=W=256, CD=TD=128, C=256, WS=8, SHIFT=4, NH=4, HD=32
//   M = B*H*W = 131072 pixels; window count NW=1024, N=64 per window.
// ---------------------------------------------------------------------------
#define MPIX (2 * 256 * 256)

// Scratch (device globals: allocation-free per harness rules)
__device__ float g_convx [(size_t)MPIX * 128];
__device__ float g_transx[(size_t)MPIX * 128];
__device__ float g_r     [(size_t)MPIX * 128];
__device__ float g_h     [(size_t)MPIX * 128];
__device__ float g_qkv   [(size_t)MPIX * 384];
__device__ float g_attn  [(size_t)MPIX * 128];
__device__ float g_t     [(size_t)MPIX * 128];
__device__ float g_mlp   [(size_t)MPIX * 512];

enum { M_C1 = 0, M_QKV, M_PROJ, M_GELU, M_MLP2, M_C2 };

// ---------------------------------------------------------------------------
// tf32 helpers
// ---------------------------------------------------------------------------
__device__ __forceinline__ float to_tf32(float x) {
    float r;
    asm("cvt.rna.tf32.f32 %0, %1;" : "=f"(r) : "f"(x));
    return r;
}

__device__ __forceinline__ void mma_tf32(float d[4], const unsigned a[4],
                                         const unsigned b[2]) {
    asm volatile(
        "mma.sync.aligned.m16n8k8.row.col.f32.tf32.tf32.f32 "
        "{%0,%1,%2,%3}, {%4,%5,%6,%7}, {%8,%9}, {%0,%1,%2,%3};"
        : "+f"(d[0]), "+f"(d[1]), "+f"(d[2]), "+f"(d[3])
        : "r"(a[0]), "r"(a[1]), "r"(a[2]), "r"(a[3]), "r"(b[0]), "r"(b[1]));
}

// One BK=16 chunk of MMAs for one warp (2 k8 steps, 4x4 fragment grid).
// As/Bs: [16][136] tf32-valued smem tiles ([k][m] / [k][n]).
__device__ __forceinline__ void mma_chunk(const float (*As)[136],
                                          const float (*Bs)[136],
                                          int wm, int wn, int g, int tg,
                                          float (*dacc)[4][4]) {
#pragma unroll
    for (int ks = 0; ks < 2; ++ks) {
        const int k0 = ks * 8;
        unsigned afr[4][4], bfr[4][2];
#pragma unroll
        for (int i = 0; i < 4; ++i) {
            int mb = wm * 64 + i * 16;
            afr[i][0] = __float_as_uint(As[k0 + tg    ][mb + g]);
            afr[i][1] = __float_as_uint(As[k0 + tg    ][mb + g + 8]);
            afr[i][2] = __float_as_uint(As[k0 + tg + 4][mb + g]);
            afr[i][3] = __float_as_uint(As[k0 + tg + 4][mb + g + 8]);
        }
#pragma unroll
        for (int j = 0; j < 4; ++j) {
            int nb = wn * 32 + j * 8;
            bfr[j][0] = __float_as_uint(Bs[k0 + tg    ][nb + g]);
            bfr[j][1] = __float_as_uint(Bs[k0 + tg + 4][nb + g]);
        }
#pragma unroll
        for (int i = 0; i < 4; ++i)
#pragma unroll
            for (int j = 0; j < 4; ++j)
                mma_tf32(dacc[i][j], afr[i], bfr[j]);
    }
}

// ---------------------------------------------------------------------------
// Generic tiled GEMM (tf32 tensor cores): OUT = A @ W + epilogue
// BM=BN=128, BK=16, 256 threads (8 warps 2x4), warp tile 64x32, m16n8k8 mma.
// ---------------------------------------------------------------------------
template <int K, int N, int MODE>
__global__ __launch_bounds__(256, 2)
void gemm_kernel(const float* __restrict__ A, const float* __restrict__ A2,
                 const float* __restrict__ Wm, const float* __restrict__ bias,
                 const float* __restrict__ res, float* __restrict__ out,
                 float* __restrict__ out2)
{
    constexpr int BM = 128, BK = 16;
    constexpr int KC = K / BK;
    __shared__ float As[2][BK][136];
    __shared__ float Bs[2][BK][136];

    const int tid = threadIdx.x;
    const int m0 = blockIdx.y * BM;
    const int n0 = blockIdx.x * 128;
    const int lane = tid & 31, wid = tid >> 5;
    const int wm = wid >> 2, wn = wid & 3;      // 2 x 4 warp grid
    const int g = lane >> 2, tg = lane & 3;

    float dacc[4][4][4];
#pragma unroll
    for (int i = 0; i < 4; ++i)
#pragma unroll
        for (int j = 0; j < 4; ++j)
#pragma unroll
            for (int r = 0; r < 4; ++r) dacc[i][j][r] = 0.f;

    float4 ar[2], br[2];

    auto gload = [&](int kc) {
#pragma unroll
        for (int it = 0; it < 2; ++it) {
            int idx4 = tid + it * 256;           // 512 float4 slots of A tile
            int ml = idx4 >> 2;
            int kl = (idx4 & 3) << 2;
            int m = m0 + ml;
            int k = kc * BK + kl;
            const float* src;
            if (MODE == M_C2) {                   // A = concat(convx, t) along K
                src = (k < 128) ? (A  + (size_t)m * 128 + k)
                                : (A2 + (size_t)m * 128 + (k - 128));
            } else {
                src = A + (size_t)m * K + k;
            }
            ar[it] = *(const float4*)src;
        }
#pragma unroll
        for (int it = 0; it < 2; ++it) {
            int idx4 = tid + it * 256;           // 512 float4 slots of B tile
            int kl = idx4 >> 5;
            int nl = (idx4 & 31) << 2;
            br[it] = *(const float4*)(Wm + (size_t)(kc * BK + kl) * N + n0 + nl);
        }
    };
    auto sstore = [&](int buf) {
#pragma unroll
        for (int it = 0; it < 2; ++it) {
            int idx4 = tid + it * 256;
            int ml = idx4 >> 2;
            int kl = (idx4 & 3) << 2;
            As[buf][kl + 0][ml] = to_tf32(ar[it].x);
            As[buf][kl + 1][ml] = to_tf32(ar[it].y);
            As[buf][kl + 2][ml] = to_tf32(ar[it].z);
            As[buf][kl + 3][ml] = to_tf32(ar[it].w);
        }
#pragma unroll
        for (int it = 0; it < 2; ++it) {
            int idx4 = tid + it * 256;
            int kl = idx4 >> 5;
            int nl = (idx4 & 31) << 2;
            float4 v;
            v.x = to_tf32(br[it].x); v.y = to_tf32(br[it].y);
            v.z = to_tf32(br[it].z); v.w = to_tf32(br[it].w);
            *(float4*)&Bs[buf][kl][nl] = v;
        }
    };

    gload(0);
    sstore(0);
    __syncthreads();

    for (int kc = 0; kc < KC; ++kc) {
        int buf = kc & 1;
        if (kc + 1 < KC) gload(kc + 1);
        mma_chunk(As[buf], Bs[buf], wm, wn, g, tg, dacc);
        if (kc + 1 < KC) sstore(buf ^ 1);
        __syncthreads();
    }

    // Epilogue: d0/d1 are adjacent columns -> float2 stores.
#pragma unroll
    for (int i = 0; i < 4; ++i) {
#pragma unroll
        for (int r2 = 0; r2 < 2; ++r2) {
            int m = m0 + wm * 64 + i * 16 + g + r2 * 8;
            size_t mout = 0;
            if (MODE == M_PROJ) {
                // window-layout m = b*65536 + w*64 + idx -> pixel (unshift roll)
                int b   = m >> 16;
                int w   = (m >> 6) & 1023;
                int idx = m & 63;
                int sh = ((w >> 5) << 3) + (idx >> 3);
                int sw = ((w & 31) << 3) + (idx & 7);
                int oh = (sh + 4) & 255;
                int ow = (sw + 4) & 255;
                mout = (size_t)((b << 16) + (oh << 8) + ow);
            }
#pragma unroll
            for (int j = 0; j < 4; ++j) {
                int n = n0 + wn * 32 + j * 8 + tg * 2;
                float v0 = dacc[i][j][r2 * 2 + 0] + bias[n];
                float v1 = dacc[i][j][r2 * 2 + 1] + bias[n + 1];
                if (MODE == M_C1) {
                    if (n < 128)
                        *(float2*)(out  + (size_t)m * 128 + n)       = make_float2(v0, v1);
                    else
                        *(float2*)(out2 + (size_t)m * 128 + n - 128) = make_float2(v0, v1);
                } else if (MODE == M_QKV) {
                    *(float2*)(out + (size_t)m * N + n) = make_float2(v0, v1);
                } else if (MODE == M_PROJ) {
                    float2 rr = *(const float2*)(res + mout * 128 + n);
                    *(float2*)(out + mout * 128 + n) =
                        make_float2(rr.x + v0, rr.y + v1);
                } else if (MODE == M_GELU) {
                    v0 = 0.5f * v0 * (1.0f + erff(v0 * 0.70710678118654752f));
                    v1 = 0.5f * v1 * (1.0f + erff(v1 * 0.70710678118654752f));
                    *(float2*)(out + (size_t)m * N + n) = make_float2(v0, v1);
                } else if (MODE == M_MLP2) {
                    float2 rr = *(const float2*)(res + (size_t)m * 128 + n);
                    *(float2*)(out + (size_t)m * 128 + n) =
                        make_float2(rr.x + v0, rr.y + v1);
                } else { // M_C2
                    float2 rr = *(const float2*)(res + (size_t)m * 256 + n);
                    *(float2*)(out + (size_t)m * 256 + n) =
                        make_float2(rr.x + v0, rr.y + v1);
                }
            }
        }
    }
}

// ---------------------------------------------------------------------------
// 3x3 SAME conv as implicit GEMM (tf32 tensor cores): K=1152, N=128.
// MODE 0: out = lrelu(acc+bias)      MODE 1: out = lrelu(acc+bias) + 2*out
// ---------------------------------------------------------------------------
template <int MODE>
__global__ __launch_bounds__(256, 2)
void conv3x3_kernel(const float* __restrict__ src, const float* __restrict__ Wm,
                    const float* __restrict__ bias, float* __restrict__ out)
{
    constexpr int BK = 16, K = 1152;
    constexpr int KC = K / BK;
    __shared__ float As[2][BK][136];
    __shared__ float Bs[2][BK][136];

    const int tid = threadIdx.x;
    const int m0 = blockIdx.y * 128;      // 128 consecutive pixels: same (b,h)
    const int lane = tid & 31, wid = tid >> 5;
    const int wm = wid >> 2, wn = wid & 3;
    const int g = lane >> 2, tg = lane & 3;
    const int bb    = m0 >> 16;
    const int h     = (m0 >> 8) & 255;
    const int wbase = m0 & 255;           // 0 or 128

    float dacc[4][4][4];
#pragma unroll
    for (int i = 0; i < 4; ++i)
#pragma unroll
        for (int j = 0; j < 4; ++j)
#pragma unroll
            for (int r = 0; r < 4; ++r) dacc[i][j][r] = 0.f;

    float4 ar[2], br[2];

    auto gload = [&](int kc) {
        int k0   = kc * BK;
        int kh   = k0 / 384;
        int kwr  = (k0 / 128) % 3;
        int cin0 = k0 & 127;
        int ih   = h + kh - 1;
        bool rowok = ((unsigned)ih < 256u);
#pragma unroll
        for (int it = 0; it < 2; ++it) {
            int idx4 = tid + it * 256;
            int ml = idx4 >> 2;
            int kl = (idx4 & 3) << 2;
            int iw = wbase + ml + kwr - 1;
            float4 v = make_float4(0.f, 0.f, 0.f, 0.f);
            if (rowok && (unsigned)iw < 256u)
                v = *(const float4*)(src +
                        (((size_t)bb * 256 + ih) * 256 + iw) * 128 + cin0 + kl);
            ar[it] = v;
        }
#pragma unroll
        for (int it = 0; it < 2; ++it) {
            int idx4 = tid + it * 256;
            int kl = idx4 >> 5;
            int nl = (idx4 & 31) << 2;
            br[it] = *(const float4*)(Wm + (size_t)(k0 + kl) * 128 + nl);
        }
    };
    auto sstore = [&](int buf) {
#pragma unroll
        for (int it = 0; it < 2; ++it) {
            int idx4 = tid + it * 256;
            int ml = idx4 >> 2;
            int kl = (idx4 & 3) << 2;
            As[buf][kl + 0][ml] = to_tf32(ar[it].x);
            As[buf][kl + 1][ml] = to_tf32(ar[it].y);
            As[buf][kl + 2][ml] = to_tf32(ar[it].z);
            As[buf][kl + 3][ml] = to_tf32(ar[it].w);
        }
#pragma unroll
        for (int it = 0; it < 2; ++it) {
            int idx4 = tid + it * 256;
            int kl = idx4 >> 5;
            int nl = (idx4 & 31) << 2;
            float4 v;
            v.x = to_tf32(br[it].x); v.y = to_tf32(br[it].y);
            v.z = to_tf32(br[it].z); v.w = to_tf32(br[it].w);
            *(float4*)&Bs[buf][kl][nl] = v;
        }
    };

    gload(0);
    sstore(0);
    __syncthreads();

    for (int kc = 0; kc < KC; ++kc) {
        int buf = kc & 1;
        if (kc + 1 < KC) gload(kc + 1);
        mma_chunk(As[buf], Bs[buf], wm, wn, g, tg, dacc);
        if (kc + 1 < KC) sstore(buf ^ 1);
        __syncthreads();
    }

#pragma unroll
    for (int i = 0; i < 4; ++i) {
#pragma unroll
        for (int r2 = 0; r2 < 2; ++r2) {
            int m = m0 + wm * 64 + i * 16 + g + r2 * 8;
#pragma unroll
            for (int j = 0; j < 4; ++j) {
                int n = wn * 32 + j * 8 + tg * 2;
                float v0 = dacc[i][j][r2 * 2 + 0] + bias[n];
                float v1 = dacc[i][j][r2 * 2 + 1] + bias[n + 1];
                v0 = (v0 >= 0.f) ? v0 : 0.01f * v0;
                v1 = (v1 >= 0.f) ? v1 : 0.01f * v1;
                if (MODE == 0) {
                    *(float2*)(out + (size_t)m * 128 + n) = make_float2(v0, v1);
                } else {
                    float2 pr = *(const float2*)(out + (size_t)m * 128 + n);
                    *(float2*)(out + (size_t)m * 128 + n) =
                        make_float2(v0 + 2.f * pr.x, v1 + 2.f * pr.y);
                }
            }
        }
    }
}

// ---------------------------------------------------------------------------
// LayerNorm over last dim (128). One warp per pixel, float4 per lane.
// ---------------------------------------------------------------------------
__global__ void ln_kernel(const float* __restrict__ src, const float* __restrict__ g,
                          const float* __restrict__ beta, float* __restrict__ dst)
{
    int gid = blockIdx.x * blockDim.x + threadIdx.x;
    int pix = gid >> 5;
    int lane = gid & 31;
    if (pix >= MPIX) return;

    float4 v = ((const float4*)(src + (size_t)pix * 128))[lane];
    float s  = v.x + v.y + v.z + v.w;
    float sq = v.x * v.x + v.y * v.y + v.z * v.z + v.w * v.w;
#pragma unroll
    for (int o = 16; o > 0; o >>= 1) {
        s  += __shfl_xor_sync(0xffffffffu, s,  o);
        sq += __shfl_xor_sync(0xffffffffu, sq, o);
    }
    float mu  = s * (1.f / 128.f);
    float var = sq * (1.f / 128.f) - mu * mu;
    float inv = rsqrtf(var + 1e-5f);

    float4 gg = ((const float4*)g)[lane];
    float4 bb = ((const float4*)beta)[lane];
    float4 o4;
    o4.x = (v.x - mu) * inv * gg.x + bb.x;
    o4.y = (v.y - mu) * inv * gg.y + bb.y;
    o4.z = (v.z - mu) * inv * gg.z + bb.z;
    o4.w = (v.w - mu) * inv * gg.w + bb.w;
    ((float4*)(dst + (size_t)pix * 128))[lane] = o4;
}

// ---------------------------------------------------------------------------
// Shifted-window attention (fp32). One block per (batch, window).
// ---------------------------------------------------------------------------
__global__ __launch_bounds__(256)
void attn_kernel(const float* __restrict__ qkv, const float* __restrict__ rpb,
                 float* __restrict__ out)
{
    __shared__ float kv[64][128];      // holds K, then reused for V
    __shared__ float rpbs[900];        // 225 x 4
    __shared__ int   msrc[64];
    __shared__ int   regid[64];

    const int bw = blockIdx.x;         // 0..2047
    const int b  = bw >> 10;
    const int w  = bw & 1023;
    const int wh = w >> 5, ww = w & 31;
    const int tid = threadIdx.x;

    if (tid < 64) {
        int ih = tid >> 3, iw = tid & 7;
        int sh = wh * 8 + ih, sw = ww * 8 + iw;
        int oh = (sh + 4) & 255, ow = (sw + 4) & 255;   // roll(-4) gather
        msrc[tid] = (b * 256 + oh) * 256 + ow;
        int rr = (sh < 248) ? 0 : (sh < 252 ? 1 : 2);
        int cr = (sw < 248) ? 0 : (sw < 252 ? 1 : 2);
        regid[tid] = rr * 3 + cr;
    }
    for (int i = tid; i < 900; i += 256) rpbs[i] = rpb[i];
    __syncthreads();

    // ---- load K ----
#pragma unroll
    for (int it = 0; it < 8; ++it) {
        int slot = tid + it * 256;     // 2048 float4 slots
        int r = slot >> 5, c4 = slot & 31;
        size_t base = (size_t)msrc[r] * 384;
        *(float4*)&kv[r][c4 * 4] = *(const float4*)(qkv + base + 128 + c4 * 4);
    }
    __syncthreads();

    const int hd = tid >> 6;           // head
    const int i  = tid & 63;           // query row in window
    const float SCALE = 0.17677669529663687f;  // 32^-0.5

    float q[32];
    {
        size_t qb = (size_t)msrc[i] * 384 + hd * 32;
#pragma unroll
        for (int d4 = 0; d4 < 8; ++d4) {
            float4 t = *(const float4*)(qkv + qb + d4 * 4);
            q[d4 * 4 + 0] = t.x; q[d4 * 4 + 1] = t.y;
            q[d4 * 4 + 2] = t.z; q[d4 * 4 + 3] = t.w;
        }
    }

    float sc[64];
    const int idi = regid[i];
    const int ihh = i >> 3, iww = i & 7;
    float mx = -1e30f;
#pragma unroll
    for (int j = 0; j < 64; ++j) {
        float s = 0.f;
        const float* kr = &kv[j][hd * 32];
#pragma unroll
        for (int d = 0; d < 32; d += 4) {
            float4 kk = *(const float4*)(kr + d);
            s += q[d] * kk.x + q[d + 1] * kk.y + q[d + 2] * kk.z + q[d + 3] * kk.w;
        }
        s *= SCALE;
        int jh = j >> 3, jw = j & 7;
        int rel = (ihh - jh + 7) * 15 + (iww - jw + 7);
        s += rpbs[rel * 4 + hd];
        if (regid[j] != idi) s -= 1e9f;
        sc[j] = s;
        mx = fmaxf(mx, s);
    }
    float sum = 0.f;
#pragma unroll
    for (int j = 0; j < 64; ++j) {
        float e = expf(sc[j] - mx);
        sc[j] = e;
        sum += e;
    }
    float rinv = 1.f / sum;
    __syncthreads();                   // everyone done with K

    // ---- load V into same smem ----
#pragma unroll
    for (int it = 0; it < 8; ++it) {
        int slot = tid + it * 256;
        int r = slot >> 5, c4 = slot & 31;
        size_t base = (size_t)msrc[r] * 384;
        *(float4*)&kv[r][c4 * 4] = *(const float4*)(qkv + base + 256 + c4 * 4);
    }
    __syncthreads();

    float o[32];
#pragma unroll
    for (int d = 0; d < 32; ++d) o[d] = 0.f;
#pragma unroll
    for (int j = 0; j < 64; ++j) {
        float p = sc[j] * rinv;
        const float* vr = &kv[j][hd * 32];
#pragma unroll
        for (int d = 0; d < 32; d += 4) {
            float4 vv = *(const float4*)(vr + d);
            o[d]     += p * vv.x;
            o[d + 1] += p * vv.y;
            o[d + 2] += p * vv.z;
            o[d + 3] += p * vv.w;
        }
    }
    float* op = out + ((size_t)bw * 64 + i) * 128 + hd * 32;
#pragma unroll
    for (int d4 = 0; d4 < 8; ++d4)
        *(float4*)(op + d4 * 4) = make_float4(o[d4 * 4], o[d4 * 4 + 1],
                                              o[d4 * 4 + 2], o[d4 * 4 + 3]);
}

// ---------------------------------------------------------------------------
// Launcher: 11 launches, all default stream, graph-capturable, alloc-free.
// ---------------------------------------------------------------------------
extern "C" void kernel_launch(void* const* d_in, const int* in_sizes, int n_in,
                              void* d_out, int out_size)
{
    const float* x    = (const float*)d_in[0];
    const float* c1w  = (const float*)d_in[1];
    const float* c1b  = (const float*)d_in[2];
    const float* rw1  = (const float*)d_in[3];
    const float* rb1  = (const float*)d_in[4];
    const float* rw2  = (const float*)d_in[5];
    const float* rb2  = (const float*)d_in[6];
    const float* ln1g = (const float*)d_in[7];
    const float* ln1b = (const float*)d_in[8];
    const float* qkvw = (const float*)d_in[9];
    const float* qkvb = (const float*)d_in[10];
    const float* rpb  = (const float*)d_in[11];
    const float* pw   = (const float*)d_in[12];
    const float* pb   = (const float*)d_in[13];
    const float* ln2g = (const float*)d_in[14];
    const float* ln2b = (const float*)d_in[15];
    const float* mw1  = (const float*)d_in[16];
    const float* mb1  = (const float*)d_in[17];
    const float* mw2  = (const float*)d_in[18];
    const float* mb2  = (const float*)d_in[19];
    const float* c2w  = (const float*)d_in[20];
    const float* c2b  = (const float*)d_in[21];
    float* out = (float*)d_out;

    float *convx, *transx, *r, *h, *qkv, *attn, *t, *mlp;
    cudaGetSymbolAddress((void**)&convx,  g_convx);
    cudaGetSymbolAddress((void**)&transx, g_transx);
    cudaGetSymbolAddress((void**)&r,      g_r);
    cudaGetSymbolAddress((void**)&h,      g_h);
    cudaGetSymbolAddress((void**)&qkv,    g_qkv);
    cudaGetSymbolAddress((void**)&attn,   g_attn);
    cudaGetSymbolAddress((void**)&t,      g_t);
    cudaGetSymbolAddress((void**)&mlp,    g_mlp);

    dim3 blk(256);
    const int MB = MPIX / 128;   // 1024 M-tiles

    // 1. c1 (1x1 conv) -> split conv_x / trans_x
    gemm_kernel<256, 256, M_C1><<<dim3(2, MB), blk>>>(x, nullptr, c1w, c1b,
                                                      nullptr, convx, transx);
    // 2-3. conv branch: two 3x3 convs + lrelu, residual 2*conv_x
    conv3x3_kernel<0><<<dim3(1, MB), blk>>>(convx, rw1, rb1, r);
    conv3x3_kernel<1><<<dim3(1, MB), blk>>>(r, rw2, rb2, convx);

    // 4. LN1(trans_x) -> h
    ln_kernel<<<MPIX / 8, 256>>>(transx, ln1g, ln1b, h);
    // 5. qkv projection
    gemm_kernel<128, 384, M_QKV><<<dim3(3, MB), blk>>>(h, nullptr, qkvw, qkvb,
                                                       nullptr, qkv, nullptr);
    // 6. shifted-window attention (window layout out)
    attn_kernel<<<2048, 256>>>(qkv, rpb, attn);
    // 7. proj + unshift scatter + trans_x residual -> t
    gemm_kernel<128, 128, M_PROJ><<<dim3(1, MB), blk>>>(attn, nullptr, pw, pb,
                                                        transx, t, nullptr);
    // 8. LN2(t) -> h
    ln_kernel<<<MPIX / 8, 256>>>(t, ln2g, ln2b, h);
    // 9. MLP up + exact GELU
    gemm_kernel<128, 512, M_GELU><<<dim3(4, MB), blk>>>(h, nullptr, mw1, mb1,
                                                        nullptr, mlp, nullptr);
    // 10. MLP down + t residual (in-place)
    gemm_kernel<512, 128, M_MLP2><<<dim3(1, MB), blk>>>(mlp, nullptr, mw2, mb2,
                                                        t, t, nullptr);
    // 11. c2 on concat(conv_x, t) + x residual -> out
    gemm_kernel<256, 256, M_C2><<<dim3(2, MB), blk>>>(convx, t, c2w, c2b,
                                                      x, out, nullptr);
}